// round 6
// baseline (speedup 1.0000x reference)
#include <cuda_runtime.h>
#include <cstdint>

#define T_STEPS 2048
#define BATCH   32
#define HID     512

typedef unsigned long long ull;

// ---------------------------------------------------------------------------
// Scratch (device globals; no allocation allowed in kernel_launch)
// ---------------------------------------------------------------------------
__device__ float g_xw [T_STEPS * BATCH * HID];
__device__ float g_mid[T_STEPS * BATCH * HID];

// ---------------------------------------------------------------------------
// Helpers
// ---------------------------------------------------------------------------
__device__ __forceinline__ uint32_t smem_u32(const void* p) {
    uint32_t a;
    asm("{ .reg .u64 t; cvta.to.shared.u64 t, %1; cvt.u32.u64 %0, t; }"
        : "=r"(a) : "l"(p));
    return a;
}

// Store a float into the same SMEM offset of cluster CTA `rank`.
__device__ __forceinline__ void st_cluster_f32(uint32_t laddr, unsigned rank, float v) {
    asm volatile(
        "{\n\t"
        ".reg .b32 ra;\n\t"
        "mapa.shared::cluster.u32 ra, %0, %1;\n\t"
        "st.shared::cluster.f32 [ra], %2;\n\t"
        "}"
        :: "r"(laddr), "r"(rank), "f"(v) : "memory");
}

__device__ __forceinline__ void cluster_arrive() {
    asm volatile("barrier.cluster.arrive.aligned;" ::: "memory");
}
__device__ __forceinline__ void cluster_wait() {
    asm volatile("barrier.cluster.wait.aligned;" ::: "memory");
}

// Packed fp32x2 FMA (Blackwell FFMA2)
__device__ __forceinline__ ull fma2(ull a, ull b, ull c) {
    ull d;
    asm("fma.rn.f32x2 %0, %1, %2, %3;" : "=l"(d) : "l"(a), "l"(b), "l"(c));
    return d;
}
__device__ __forceinline__ float f2_lo(ull v) { return __uint_as_float((unsigned)(v & 0xFFFFFFFFull)); }
__device__ __forceinline__ float f2_hi(ull v) { return __uint_as_float((unsigned)(v >> 32)); }
__device__ __forceinline__ ull splat2(float f) {
    ull d;
    asm("mov.b64 %0, {%1, %1};" : "=l"(d) : "f"(f));
    return d;
}

// ---------------------------------------------------------------------------
// Kernel 1: xw = X(M,512) @ W(512,512)^T + (b1 + b2)
//   M = 65536, N = 512, K = 512. Tile 128x64, BK=16, 256 threads.
//   FFMA2 micro-kernel: accumulators packed over adjacent M rows
//   (16 FFMA2 per k-step instead of 32 scalar FFMA).
// ---------------------------------------------------------------------------
__global__ void __launch_bounds__(256)
gemm_xw_kernel(const float* __restrict__ X,
               const float* __restrict__ W,
               const float* __restrict__ b1,
               const float* __restrict__ b2,
               float* __restrict__ Y)
{
    __shared__ __align__(16) float As[16][132];   // [k][m]; row stride 528B
    __shared__ __align__(16) float Bs[16][68];    // [k][n]; row stride 272B

    const int tid = threadIdx.x;
    const int m0 = blockIdx.x * 128;
    const int n0 = blockIdx.y * 64;
    const int ty = tid >> 4;        // rows ty*8 .. ty*8+7
    const int tx = tid & 15;        // cols tx*4 .. tx*4+3

    const int am = tid >> 1;
    const int ak = (tid & 1) * 8;
    const int bn = tid >> 2;
    const int bk = (tid & 3) * 4;

    // acc2[i2][j]: packed (row 2*i2, row 2*i2+1) accumulators for column j
    ull acc2[4][4];
#pragma unroll
    for (int i = 0; i < 4; i++)
#pragma unroll
        for (int j = 0; j < 4; j++) acc2[i][j] = 0ull;

    const float* Xr = X + (size_t)(m0 + am) * 512;
    const float* Wr = W + (size_t)(n0 + bn) * 512;

    for (int kb = 0; kb < 512; kb += 16) {
        float4 a0 = *(const float4*)(Xr + kb + ak);
        float4 a1 = *(const float4*)(Xr + kb + ak + 4);
        float4 bv = *(const float4*)(Wr + kb + bk);
        __syncthreads();
        As[ak + 0][am] = a0.x; As[ak + 1][am] = a0.y;
        As[ak + 2][am] = a0.z; As[ak + 3][am] = a0.w;
        As[ak + 4][am] = a1.x; As[ak + 5][am] = a1.y;
        As[ak + 6][am] = a1.z; As[ak + 7][am] = a1.w;
        Bs[bk + 0][bn] = bv.x; Bs[bk + 1][bn] = bv.y;
        Bs[bk + 2][bn] = bv.z; Bs[bk + 3][bn] = bv.w;
        __syncthreads();
#pragma unroll
        for (int k = 0; k < 16; k++) {
            // a pairs: (m0,m1),(m2,m3),(m4,m5),(m6,m7) — direct reinterpret
            ulonglong2 ap0 = *(const ulonglong2*)&As[k][ty * 8];
            ulonglong2 ap1 = *(const ulonglong2*)&As[k][ty * 8 + 4];
            float4 b4 = *(const float4*)&Bs[k][tx * 4];
            ull bs0 = splat2(b4.x), bs1 = splat2(b4.y);
            ull bs2 = splat2(b4.z), bs3 = splat2(b4.w);
            acc2[0][0] = fma2(ap0.x, bs0, acc2[0][0]);
            acc2[0][1] = fma2(ap0.x, bs1, acc2[0][1]);
            acc2[0][2] = fma2(ap0.x, bs2, acc2[0][2]);
            acc2[0][3] = fma2(ap0.x, bs3, acc2[0][3]);
            acc2[1][0] = fma2(ap0.y, bs0, acc2[1][0]);
            acc2[1][1] = fma2(ap0.y, bs1, acc2[1][1]);
            acc2[1][2] = fma2(ap0.y, bs2, acc2[1][2]);
            acc2[1][3] = fma2(ap0.y, bs3, acc2[1][3]);
            acc2[2][0] = fma2(ap1.x, bs0, acc2[2][0]);
            acc2[2][1] = fma2(ap1.x, bs1, acc2[2][1]);
            acc2[2][2] = fma2(ap1.x, bs2, acc2[2][2]);
            acc2[2][3] = fma2(ap1.x, bs3, acc2[2][3]);
            acc2[3][0] = fma2(ap1.y, bs0, acc2[3][0]);
            acc2[3][1] = fma2(ap1.y, bs1, acc2[3][1]);
            acc2[3][2] = fma2(ap1.y, bs2, acc2[3][2]);
            acc2[3][3] = fma2(ap1.y, bs3, acc2[3][3]);
        }
    }

    float bias[4];
#pragma unroll
    for (int j = 0; j < 4; j++)
        bias[j] = b1[n0 + tx * 4 + j] + b2[n0 + tx * 4 + j];

#pragma unroll
    for (int i2 = 0; i2 < 4; i2++) {
        const int row_lo = m0 + ty * 8 + 2 * i2;
        float4 olo, ohi;
        olo.x = f2_lo(acc2[i2][0]) + bias[0];
        olo.y = f2_lo(acc2[i2][1]) + bias[1];
        olo.z = f2_lo(acc2[i2][2]) + bias[2];
        olo.w = f2_lo(acc2[i2][3]) + bias[3];
        ohi.x = f2_hi(acc2[i2][0]) + bias[0];
        ohi.y = f2_hi(acc2[i2][1]) + bias[1];
        ohi.z = f2_hi(acc2[i2][2]) + bias[2];
        ohi.w = f2_hi(acc2[i2][3]) + bias[3];
        *(float4*)&Y[(size_t)row_lo * 512 + n0 + tx * 4]       = olo;
        *(float4*)&Y[(size_t)(row_lo + 1) * 512 + n0 + tx * 4] = ohi;
    }
}

// ---------------------------------------------------------------------------
// Kernel 2: persistent recurrent scan — PROVEN barrier.cluster sync (as in the
//   two passing rounds), with warp-local shfl reduce and 2x-wider tail.
//   16 clusters x 8 CTAs; cluster g owns batches {2g,2g+1}; CTA rank c owns
//   rows [64c,64c+64). W slice in registers (128 floats/thread).
//   tid = r*4+q: q = k-quarter in lane bits -> shfl.bfly reduce over q.
//   h in SMEM as [buf][batch][4 x 132 floats] (528B quarter stride -> the 4
//   q-group LDS.128 broadcasts are bank-conflict-free).
//   Tail: q==0 lanes own batch 0, q==1 lanes own batch 1 (shfl leaves sums in
//   all lanes): tanh, DSMEM all-gather (8 st.shared::cluster), then
//   arrive -> OUT store + next-XW prefetch -> wait.
// ---------------------------------------------------------------------------
#define QPAD 132            // padded floats per k-quarter
#define HB   (4 * QPAD)     // floats per (buf,batch) = 528

__global__ void __cluster_dims__(8, 1, 1) __launch_bounds__(256, 1)
rnn_scan_kernel(const float* __restrict__ Whh,
                const float* __restrict__ XW,
                float* __restrict__ OUT)
{
    __shared__ __align__(16) float sH[2][2][HB];   // [buf][batch][padded 512]

    const int tid = threadIdx.x;
    unsigned rank;
    asm("mov.u32 %0, %%cluster_ctarank;" : "=r"(rank));
    const int group = blockIdx.x >> 3;
    const int b0 = group * 2;

    const int q = tid & 3;                 // k-quarter (warp-local lane bits)
    const int r = tid >> 2;                // local row 0..63
    const int rowG = (int)rank * 64 + r;
    const bool tail = (q < 2);             // q==0 -> batch 0, q==1 -> batch 1

    // ---- W registers: row rowG, k in [q*128, q*128+128) as 32 ulonglong2 ----
    ulonglong2 w[32];
    {
        const ulonglong2* Wg = (const ulonglong2*)(Whh + (size_t)rowG * 512) + q * 32;
#pragma unroll
        for (int j = 0; j < 32; j++) w[j] = Wg[j];
    }

    // ---- h_0 = 0 (buf 0, both batches, incl. padding) ----
    for (int i = tid; i < 2 * HB; i += 256) sH[0][0][i] = 0.f;
    __syncthreads();
    cluster_arrive();
    cluster_wait();

    // Padded offset of this thread's row within a batch region
    const int wOff = (rowG >> 7) * QPAD + (rowG & 127);

    // Prime xw prefetch for t = 0 (tail lanes: q is the batch index)
    float xv = 0.f;
    if (tail)
        xv = XW[(size_t)(0 * BATCH + b0 + q) * 512 + rowG];

    for (int t = 0; t < T_STEPS; t++) {
        const float (*hc)[HB] = sH[t & 1];
        float       (*hn)[HB] = sH[(t + 1) & 1];

        // Prefetch NEXT step's xw early (LDG latency hidden under matvec)
        float nxv = 0.f;
        if (tail && (t + 1 < T_STEPS))
            nxv = XW[(size_t)((t + 1) * BATCH + b0 + q) * 512 + rowG];

        // ---- FFMA2 matvec over this thread's k-quarter ----
        const ulonglong2* h0 = (const ulonglong2*)(&hc[0][q * QPAD]);  // batch b0
        const ulonglong2* h1 = (const ulonglong2*)(&hc[1][q * QPAD]);  // batch b0+1
        ull a0x = 0, a0y = 0, a1x = 0, a1y = 0;
#pragma unroll
        for (int j = 0; j < 32; j++) {
            const ulonglong2 ha = h0[j];
            const ulonglong2 hb = h1[j];
            a0x = fma2(w[j].x, ha.x, a0x);
            a0y = fma2(w[j].y, ha.y, a0y);
            a1x = fma2(w[j].x, hb.x, a1x);
            a1y = fma2(w[j].y, hb.y, a1y);
        }
        float acc0 = (f2_lo(a0x) + f2_hi(a0x)) + (f2_lo(a0y) + f2_hi(a0y));
        float acc1 = (f2_lo(a1x) + f2_hi(a1x)) + (f2_lo(a1y) + f2_hi(a1y));

        // ---- warp-local reduce over q (lane bits 0..1); sums land in ALL lanes
        acc0 += __shfl_xor_sync(0xFFFFFFFFu, acc0, 1);
        acc1 += __shfl_xor_sync(0xFFFFFFFFu, acc1, 1);
        acc0 += __shfl_xor_sync(0xFFFFFFFFu, acc0, 2);
        acc1 += __shfl_xor_sync(0xFFFFFFFFu, acc1, 2);

        // ---- tail lanes: tanh + DSMEM all-gather (before arrive) ----
        float v = 0.f;
        if (tail) {
            v = tanhf((q == 0 ? acc0 : acc1) + xv);
            if (t + 1 < T_STEPS) {
                const uint32_t la = smem_u32(&hn[q][wOff]);
#pragma unroll
                for (unsigned pr = 0; pr < 8; pr++)
                    st_cluster_f32(la, pr, v);
            }
        }

        // Release DSMEM stores; overlap global traffic with barrier drain.
        cluster_arrive();

        if (tail) {
            OUT[(size_t)(t * BATCH + b0 + q) * 512 + rowG] = v;
            xv = nxv;
        }

        cluster_wait();
    }
}

// ---------------------------------------------------------------------------
// Launch
// ---------------------------------------------------------------------------
extern "C" void kernel_launch(void* const* d_in, const int* in_sizes, int n_in,
                              void* d_out, int out_size)
{
    const float* x    = (const float*)d_in[0];
    const float* wih0 = (const float*)d_in[1];
    const float* whh0 = (const float*)d_in[2];
    const float* bih0 = (const float*)d_in[3];
    const float* bhh0 = (const float*)d_in[4];
    const float* wih1 = (const float*)d_in[5];
    const float* whh1 = (const float*)d_in[6];
    const float* bih1 = (const float*)d_in[7];
    const float* bhh1 = (const float*)d_in[8];
    float* out = (float*)d_out;

    float *xw = nullptr, *mid = nullptr;
    cudaGetSymbolAddress((void**)&xw,  g_xw);
    cudaGetSymbolAddress((void**)&mid, g_mid);

    const dim3 ggrid(512, 8);

    gemm_xw_kernel<<<ggrid, 256>>>(x,   wih0, bih0, bhh0, xw);
    rnn_scan_kernel<<<128, 256>>>(whh0, xw, mid);
    gemm_xw_kernel<<<ggrid, 256>>>(mid, wih1, bih1, bhh1, xw);
    rnn_scan_kernel<<<128, 256>>>(whh1, xw, out);
}